// round 9
// baseline (speedup 1.0000x reference)
#include <cuda_runtime.h>
#include <cuda_fp16.h>

#define NN 100000
#define EE 1600000
#define TPB 256

typedef unsigned long long u64;

// ---- scratch (__device__ globals; no allocations allowed) ----
__device__ __half   g_xlh[NN * 64];   // fp16 x @ Wl + bl (logits + messages)
__device__ __half   g_xrh[NN * 64];   // fp16 x @ Wr + br (logits only)
__device__ float4   g_denom[NN];      // per-head softmax denominators
__device__ float2   g_gate2[NN];      // {gate_sum, degree} per target

// ---- small params in constant memory ----
__constant__ __align__(16) float cWe[1024];   // [16,64]
__constant__ __align__(16) float cWg1[512];   // [16,32]
__constant__ __align__(16) float cWg2[32];
__constant__ __align__(16) float cbg1[32];
__constant__ __align__(16) float catt[64];
__constant__ __align__(16) float cbias[64];
__constant__ __align__(16) float cgamma[64];
__constant__ __align__(16) float cbeta[64];
__constant__ float cbg2[1];

__device__ __forceinline__ float sigmoidf_(float v) {
    return 1.f / (1.f + __expf(-v));
}
__device__ __forceinline__ u64 pack2(float lo, float hi) {
    u64 r; asm("mov.b64 %0, {%1,%2};" : "=l"(r) : "f"(lo), "f"(hi)); return r;
}
__device__ __forceinline__ void unpack2(u64 v, float& lo, float& hi) {
    asm("mov.b64 {%0,%1}, %2;" : "=f"(lo), "=f"(hi) : "l"(v));
}
__device__ __forceinline__ void fma2(u64& d, u64 a, u64 b) {
    asm("fma.rn.f32x2 %0, %1, %2, %0;" : "+l"(d) : "l"(a), "l"(b));
}
__device__ __forceinline__ void red4(float* p, float a, float b, float c, float d) {
    asm volatile("red.global.add.v4.f32 [%0], {%1,%2,%3,%4};"
                 :: "l"(p), "f"(a), "f"(b), "f"(c), "f"(d) : "memory");
}
__device__ __forceinline__ void red2(float* p, float a, float b) {
    asm volatile("red.global.add.v2.f32 [%0], {%1,%2};"
                 :: "l"(p), "f"(a), "f"(b) : "memory");
}
__device__ __forceinline__ float leaky(float m) { return fmaxf(m, 0.2f * m); }
__device__ __forceinline__ unsigned h2_bits(__half2 v) {
    return *reinterpret_cast<unsigned*>(&v);
}

// ---------------------------------------------------------------------------
// Kernel 1: node transforms (fp16 out) + init accumulators + zero d_out.
// (round-3/7 structure, measured ~42us)
// ---------------------------------------------------------------------------
__global__ void __launch_bounds__(256) k_prep(
        const float* __restrict__ x,
        const float* __restrict__ Wl, const float* __restrict__ bl,
        const float* __restrict__ Wr, const float* __restrict__ br,
        float* __restrict__ out) {
    __shared__ __align__(16) float Ws[64 * 128];
    __shared__ __align__(16) float xs[64 * 64];
    int t = threadIdx.x;
    int nb = blockIdx.x * 64;

#pragma unroll
    for (int i = 0; i < 16; i++) {
        int idx = t + i * 256;
        int k = idx >> 6, c = idx & 63;
        Ws[k * 128 + c]      = Wl[idx];
        Ws[k * 128 + 64 + c] = Wr[idx];
    }
#pragma unroll
    for (int i = 0; i < 16; i++) {
        int idx = t + i * 256;
        int n = nb + (idx >> 6);
        bool ok = n < NN;
        xs[idx] = ok ? x[(size_t)n * 64 + (idx & 63)] : 0.f;
        if (ok) out[(size_t)n * 64 + (idx & 63)] = 0.f;
    }
    if (t < 64) {
        int n = nb + t;
        if (n < NN) {
            g_denom[n] = make_float4(0.f, 0.f, 0.f, 0.f);
            g_gate2[n] = make_float2(0.f, 0.f);
        }
    }
    __syncthreads();

    int cg = t & 31, ng = t >> 5;
    int c0 = cg * 4;
    const float* bsrc = (c0 < 64) ? (bl + c0) : (br + (c0 - 64));
    float4 bias = *(const float4*)bsrc;

    u64 acc[8][2];
#pragma unroll
    for (int j = 0; j < 8; j++) {
        acc[j][0] = pack2(bias.x, bias.y);
        acc[j][1] = pack2(bias.z, bias.w);
    }

    for (int k4 = 0; k4 < 16; k4++) {
        float4 xv[8];
#pragma unroll
        for (int j = 0; j < 8; j++)
            xv[j] = *(const float4*)&xs[(ng * 8 + j) * 64 + k4 * 4];
#pragma unroll
        for (int kk = 0; kk < 4; kk++) {
            float4 wv = *(const float4*)&Ws[(k4 * 4 + kk) * 128 + c0];
            u64 w01 = pack2(wv.x, wv.y), w23 = pack2(wv.z, wv.w);
#pragma unroll
            for (int j = 0; j < 8; j++) {
                float xsc = (kk == 0) ? xv[j].x : (kk == 1) ? xv[j].y
                          : (kk == 2) ? xv[j].z : xv[j].w;
                u64 xx = pack2(xsc, xsc);
                fma2(acc[j][0], xx, w01);
                fma2(acc[j][1], xx, w23);
            }
        }
    }

    __half* dsth = (c0 < 64) ? g_xlh : g_xrh;
    int cc = c0 & 63;
#pragma unroll
    for (int j = 0; j < 8; j++) {
        int n = nb + ng * 8 + j;
        if (n < NN) {
            float o0, o1, o2, o3;
            unpack2(acc[j][0], o0, o1);
            unpack2(acc[j][1], o2, o3);
            uint2 p;
            p.x = h2_bits(__floats2half2_rn(o0, o1));
            p.y = h2_bits(__floats2half2_rn(o2, o3));
            *(uint2*)&dsth[(size_t)n * 64 + cc] = p;
        }
    }
}

// ---------------------------------------------------------------------------
// Kernel 2 (fused edge pass): 4 lanes per edge, ONE HEAD PER LANE.
// No shared memory, no barriers — all reductions lane-local or tiny shfls.
//   lane h of an edge group: gathers its head's 32B fp16 xl/xr chunks (LDG),
//   computes alpha_h fully locally, exp, scatters its 64B message block.
//   Gate MLP: 8 hidden units per lane + shfl.bfly reduce.
// ---------------------------------------------------------------------------
#define ETPB 256
__global__ void __launch_bounds__(ETPB) k_edge(
        const int* __restrict__ ei, const float* __restrict__ eag,
        float* __restrict__ out) {
    int t = threadIdx.x;
    int lane = t & 31;
    int h  = lane & 3;                       // head owned by this lane
    int gb = lane & ~3;                      // group leader lane
    int e  = (blockIdx.x * ETPB + t) >> 2;   // 4 lanes per edge; EE*4 % ETPB == 0

    int src = ei[e];
    int tgt = ei[EE + e];

    // ---- issue all gathers up front (latency overlapped by gate math) ----
    const __half* xlp = g_xlh + (size_t)src * 64 + h * 16;
    const __half* xrp = g_xrh + (size_t)tgt * 64 + h * 16;
    uint4 l0 = *(const uint4*)xlp;
    uint4 l1 = *(const uint4*)(xlp + 8);
    uint4 r0 = *(const uint4*)xrp;
    uint4 r1 = *(const uint4*)(xrp + 8);
    float4 eaq = *(const float4*)(eag + (size_t)e * 16 + h * 4);

    // ---- assemble full ea[16] via shfl from the 4 quarter-loads ----
    float ea[16];
#pragma unroll
    for (int i = 0; i < 4; i++) {
        ea[i * 4 + 0] = __shfl_sync(0xFFFFFFFFu, eaq.x, gb + i);
        ea[i * 4 + 1] = __shfl_sync(0xFFFFFFFFu, eaq.y, gb + i);
        ea[i * 4 + 2] = __shfl_sync(0xFFFFFFFFu, eaq.z, gb + i);
        ea[i * 4 + 3] = __shfl_sync(0xFFFFFFFFu, eaq.w, gb + i);
    }

    // ---- gate MLP: hidden units [8h, 8h+8) on this lane ----
    float gate;
    {
        u64 h2[4];
        const u64* bg1p = (const u64*)cbg1;
#pragma unroll
        for (int j = 0; j < 4; j++) h2[j] = bg1p[h * 4 + j];
        const u64* wg1p = (const u64*)cWg1;
#pragma unroll
        for (int i = 0; i < 16; i++) {
            u64 a2 = pack2(ea[i], ea[i]);
#pragma unroll
            for (int j = 0; j < 4; j++) fma2(h2[j], a2, wg1p[i * 16 + h * 4 + j]);
        }
        float gacc = 0.f;
#pragma unroll
        for (int j = 0; j < 4; j++) {
            float h0, h1; unpack2(h2[j], h0, h1);
            gacc += h0 * sigmoidf_(h0) * cWg2[h * 8 + 2 * j] +
                    h1 * sigmoidf_(h1) * cWg2[h * 8 + 2 * j + 1];
        }
        gacc += __shfl_xor_sync(0xFFFFFFFFu, gacc, 1);
        gacc += __shfl_xor_sync(0xFFFFFFFFu, gacc, 2);
        gate = sigmoidf_(gacc + cbg2[0]);
    }

    // ---- logits for head h (fully lane-local) ----
    u64 s2[8];
    float xlv[16];
    {
        const unsigned* lw = (const unsigned*)&l0;
        const unsigned* rw = (const unsigned*)&r0;
#pragma unroll
        for (int p = 0; p < 4; p++) {
            float2 lf = __half22float2(*(const __half2*)&lw[p]);
            float2 rf = __half22float2(*(const __half2*)&rw[p]);
            xlv[2 * p] = lf.x; xlv[2 * p + 1] = lf.y;
            s2[p] = pack2(lf.x + rf.x, lf.y + rf.y);
        }
        lw = (const unsigned*)&l1;
        rw = (const unsigned*)&r1;
#pragma unroll
        for (int p = 0; p < 4; p++) {
            float2 lf = __half22float2(*(const __half2*)&lw[p]);
            float2 rf = __half22float2(*(const __half2*)&rw[p]);
            xlv[8 + 2 * p] = lf.x; xlv[8 + 2 * p + 1] = lf.y;
            s2[4 + p] = pack2(lf.x + rf.x, lf.y + rf.y);
        }
    }
    const u64* we2p = (const u64*)cWe;
#pragma unroll
    for (int i = 0; i < 16; i++) {
        u64 a2 = pack2(ea[i], ea[i]);
#pragma unroll
        for (int p = 0; p < 8; p++)
            fma2(s2[p], a2, we2p[i * 32 + h * 8 + p]);
    }
    float acc = 0.f;
#pragma unroll
    for (int p = 0; p < 8; p++) {
        float m0, m1; unpack2(s2[p], m0, m1);
        acc += leaky(m0) * catt[h * 16 + 2 * p] +
               leaky(m1) * catt[h * 16 + 2 * p + 1];
    }
    float a = __expf(acc);    // no max-shift: ratios invariant, range safe

    // ---- denom + gate accumulation (leader lane of each group) ----
    float a1 = __shfl_sync(0xFFFFFFFFu, a, gb + 1);
    float a2v = __shfl_sync(0xFFFFFFFFu, a, gb + 2);
    float a3 = __shfl_sync(0xFFFFFFFFu, a, gb + 3);
    if (h == 0) {
        red4((float*)&g_denom[tgt], a, a1, a2v, a3);
        red2((float*)&g_gate2[tgt], gate, 1.f);
    }

    // ---- message scatter: this lane's 64B head block ----
    float* op = out + (size_t)tgt * 64 + h * 16;
    red4(op,      xlv[0] * a,  xlv[1] * a,  xlv[2] * a,  xlv[3] * a);
    red4(op + 4,  xlv[4] * a,  xlv[5] * a,  xlv[6] * a,  xlv[7] * a);
    red4(op + 8,  xlv[8] * a,  xlv[9] * a,  xlv[10] * a, xlv[11] * a);
    red4(op + 12, xlv[12] * a, xlv[13] * a, xlv[14] * a, xlv[15] * a);
}

// ---------------------------------------------------------------------------
// Kernel 3: node epilogue — 16 threads/node, float4 lanes, constant params.
// ---------------------------------------------------------------------------
__global__ void k_final(const float* __restrict__ x, float* __restrict__ out) {
    int gid = blockIdx.x * blockDim.x + threadIdx.x;
    int n = gid >> 4;
    int q = threadIdx.x & 15;
    int h = q >> 2;

    float2 gd = g_gate2[n];
    float mg = gd.x / fmaxf(gd.y, 1.f);
    float4 den4 = g_denom[n];
    float den = (h == 0) ? den4.x : (h == 1) ? den4.y : (h == 2) ? den4.z : den4.w;
    float inv = den > 0.f ? 1.f / den : 0.f;

    size_t idx = (size_t)n * 16 + q;
    float4 o  = ((const float4*)out)[idx];
    float4 cb = ((const float4*)cbias)[q];
    float4 v;
    v.x = (o.x * inv + cb.x) * mg;
    v.y = (o.y * inv + cb.y) * mg;
    v.z = (o.z * inv + cb.z) * mg;
    v.w = (o.w * inv + cb.w) * mg;

    float s  = v.x + v.y + v.z + v.w;
    float sq = v.x * v.x + v.y * v.y + v.z * v.z + v.w * v.w;
#pragma unroll
    for (int ofs = 1; ofs < 16; ofs <<= 1) {
        s  += __shfl_xor_sync(0xFFFFFFFFu, s,  ofs);
        sq += __shfl_xor_sync(0xFFFFFFFFu, sq, ofs);
    }
    float mu   = s * (1.f / 64.f);
    float var  = sq * (1.f / 64.f) - mu * mu;
    float rstd = rsqrtf(var + 1e-5f);

    float4 g  = ((const float4*)cgamma)[q];
    float4 bt = ((const float4*)cbeta)[q];
    float4 xv = ((const float4*)x)[idx];
    float4 r;
    float n0 = (v.x - mu) * rstd * g.x + bt.x;  n0 *= sigmoidf_(n0);  r.x = n0 + xv.x;
    float n1 = (v.y - mu) * rstd * g.y + bt.y;  n1 *= sigmoidf_(n1);  r.y = n1 + xv.y;
    float n2 = (v.z - mu) * rstd * g.z + bt.z;  n2 *= sigmoidf_(n2);  r.z = n2 + xv.z;
    float n3 = (v.w - mu) * rstd * g.w + bt.w;  n3 *= sigmoidf_(n3);  r.w = n3 + xv.w;
    ((float4*)out)[idx] = r;
}

// ---------------------------------------------------------------------------
extern "C" void kernel_launch(void* const* d_in, const int* in_sizes, int n_in,
                              void* d_out, int out_size) {
    const float* x         = (const float*)d_in[0];
    const int*   ei        = (const int*)  d_in[1];
    const float* edge_attr = (const float*)d_in[2];
    const float* Wl        = (const float*)d_in[3];
    const float* bl        = (const float*)d_in[4];
    const float* Wr        = (const float*)d_in[5];
    const float* br        = (const float*)d_in[6];
    float* out = (float*)d_out;

    cudaMemcpyToSymbolAsync(cWe,    d_in[7],  1024 * 4, 0, cudaMemcpyDeviceToDevice, 0);
    cudaMemcpyToSymbolAsync(catt,   d_in[8],  64 * 4,   0, cudaMemcpyDeviceToDevice, 0);
    cudaMemcpyToSymbolAsync(cbias,  d_in[9],  64 * 4,   0, cudaMemcpyDeviceToDevice, 0);
    cudaMemcpyToSymbolAsync(cWg1,   d_in[10], 512 * 4,  0, cudaMemcpyDeviceToDevice, 0);
    cudaMemcpyToSymbolAsync(cbg1,   d_in[11], 32 * 4,   0, cudaMemcpyDeviceToDevice, 0);
    cudaMemcpyToSymbolAsync(cWg2,   d_in[12], 32 * 4,   0, cudaMemcpyDeviceToDevice, 0);
    cudaMemcpyToSymbolAsync(cbg2,   d_in[13], 4,        0, cudaMemcpyDeviceToDevice, 0);
    cudaMemcpyToSymbolAsync(cgamma, d_in[14], 64 * 4,   0, cudaMemcpyDeviceToDevice, 0);
    cudaMemcpyToSymbolAsync(cbeta,  d_in[15], 64 * 4,   0, cudaMemcpyDeviceToDevice, 0);

    k_prep <<<(NN + 63) / 64, 256>>>(x, Wl, bl, Wr, br, out);
    k_edge <<<(EE * 4) / ETPB, ETPB>>>(ei, edge_attr, out);
    k_final<<<NN * 16 / TPB, TPB>>>(x, out);
}

// round 10
// speedup vs baseline: 9.7510x; 9.7510x over previous
#include <cuda_runtime.h>
#include <cuda_fp16.h>

#define NN 100000
#define EE 1600000
#define TPB 256
#define SCANB 391          // ceil(NN/256)

typedef unsigned long long u64;

// ---- scratch (__device__ globals; no allocations allowed) ----
__device__ __half   g_xlh[NN * 64];   // fp16 x @ Wl + bl
__device__ __half   g_xrh[NN * 64];   // fp16 x @ Wr + br
__device__ float4   g_a4[EE];         // per-edge exp(alpha) per head
__device__ float    g_gate[EE];       // per-edge gate
__device__ int2     g_sed[EE];        // CSR-grouped {src, eid}
__device__ int      g_cnt[NN];        // degree histogram
__device__ int      g_loc[NN];        // block-local exclusive scan
__device__ int      g_bsum[512];
__device__ int      g_boff[512];
__device__ int      g_off[NN + 1];    // CSR row offsets
__device__ int      g_cur[NN];        // scatter cursors

// ---- small params in constant memory (WARP-UNIFORM indexing only!) ----
__constant__ __align__(16) float cWe[1024];   // [16,64]
__constant__ __align__(16) float cWg1[512];   // [16,32]
__constant__ __align__(16) float cWg2[32];
__constant__ __align__(16) float cbg1[32];
__constant__ __align__(16) float catt[64];
__constant__ float cbg2[1];

__device__ __forceinline__ float sigmoidf_(float v) {
    return 1.f / (1.f + __expf(-v));
}
__device__ __forceinline__ u64 pack2(float lo, float hi) {
    u64 r; asm("mov.b64 %0, {%1,%2};" : "=l"(r) : "f"(lo), "f"(hi)); return r;
}
__device__ __forceinline__ void unpack2(u64 v, float& lo, float& hi) {
    asm("mov.b64 {%0,%1}, %2;" : "=f"(lo), "=f"(hi) : "l"(v));
}
__device__ __forceinline__ void fma2(u64& d, u64 a, u64 b) {
    asm("fma.rn.f32x2 %0, %1, %2, %0;" : "+l"(d) : "l"(a), "l"(b));
}
__device__ __forceinline__ float leaky(float m) { return fmaxf(m, 0.2f * m); }
__device__ __forceinline__ void cpa16(__half* smem_dst, const __half* gsrc) {
    unsigned d = (unsigned)__cvta_generic_to_shared(smem_dst);
    asm volatile("cp.async.ca.shared.global [%0], [%1], 16;"
                 :: "r"(d), "l"(gsrc) : "memory");
}
__device__ __forceinline__ unsigned h2_bits(__half2 v) {
    return *reinterpret_cast<unsigned*>(&v);
}

// ---------------------------------------------------------------------------
// Kernel 1: node transforms (fp16 out) + zero degree histogram.
// ---------------------------------------------------------------------------
__global__ void __launch_bounds__(256) k_prep(
        const float* __restrict__ x,
        const float* __restrict__ Wl, const float* __restrict__ bl,
        const float* __restrict__ Wr, const float* __restrict__ br) {
    __shared__ __align__(16) float Ws[64 * 128];
    __shared__ __align__(16) float xs[64 * 64];
    int t = threadIdx.x;
    int nb = blockIdx.x * 64;

#pragma unroll
    for (int i = 0; i < 16; i++) {
        int idx = t + i * 256;
        int k = idx >> 6, c = idx & 63;
        Ws[k * 128 + c]      = Wl[idx];
        Ws[k * 128 + 64 + c] = Wr[idx];
    }
#pragma unroll
    for (int i = 0; i < 16; i++) {
        int idx = t + i * 256;
        int n = nb + (idx >> 6);
        xs[idx] = (n < NN) ? x[(size_t)n * 64 + (idx & 63)] : 0.f;
    }
    if (t < 64 && nb + t < NN) g_cnt[nb + t] = 0;
    __syncthreads();

    int cg = t & 31, ng = t >> 5;
    int c0 = cg * 4;
    const float* bsrc = (c0 < 64) ? (bl + c0) : (br + (c0 - 64));
    float4 bias = *(const float4*)bsrc;

    u64 acc[8][2];
#pragma unroll
    for (int j = 0; j < 8; j++) {
        acc[j][0] = pack2(bias.x, bias.y);
        acc[j][1] = pack2(bias.z, bias.w);
    }

    for (int k4 = 0; k4 < 16; k4++) {
        float4 xv[8];
#pragma unroll
        for (int j = 0; j < 8; j++)
            xv[j] = *(const float4*)&xs[(ng * 8 + j) * 64 + k4 * 4];
#pragma unroll
        for (int kk = 0; kk < 4; kk++) {
            float4 wv = *(const float4*)&Ws[(k4 * 4 + kk) * 128 + c0];
            u64 w01 = pack2(wv.x, wv.y), w23 = pack2(wv.z, wv.w);
#pragma unroll
            for (int j = 0; j < 8; j++) {
                float xsc = (kk == 0) ? xv[j].x : (kk == 1) ? xv[j].y
                          : (kk == 2) ? xv[j].z : xv[j].w;
                u64 xx = pack2(xsc, xsc);
                fma2(acc[j][0], xx, w01);
                fma2(acc[j][1], xx, w23);
            }
        }
    }

    __half* dsth = (c0 < 64) ? g_xlh : g_xrh;
    int cc = c0 & 63;
#pragma unroll
    for (int j = 0; j < 8; j++) {
        int n = nb + ng * 8 + j;
        if (n < NN) {
            float o0, o1, o2, o3;
            unpack2(acc[j][0], o0, o1);
            unpack2(acc[j][1], o2, o3);
            uint2 p;
            p.x = h2_bits(__floats2half2_rn(o0, o1));
            p.y = h2_bits(__floats2half2_rn(o2, o3));
            *(uint2*)&dsth[(size_t)n * 64 + cc] = p;
        }
    }
}

// ---------------------------------------------------------------------------
// CSR construction: histogram -> scan -> scatter (round-8, measured ~30us)
// ---------------------------------------------------------------------------
__global__ void k_hist(const int* __restrict__ ei) {
    int e = blockIdx.x * blockDim.x + threadIdx.x;
    atomicAdd(&g_cnt[ei[EE + e]], 1);
}

__global__ void k_scanA() {
    __shared__ int s[256];
    int t = threadIdx.x;
    int n = blockIdx.x * 256 + t;
    int v = (n < NN) ? g_cnt[n] : 0;
    s[t] = v;
    __syncthreads();
#pragma unroll
    for (int o = 1; o < 256; o <<= 1) {
        int u = (t >= o) ? s[t - o] : 0;
        __syncthreads();
        s[t] += u;
        __syncthreads();
    }
    if (n < NN) g_loc[n] = s[t] - v;
    if (t == 255) g_bsum[blockIdx.x] = s[255];
}

__global__ void k_scanB() {
    __shared__ int s[512];
    int t = threadIdx.x;
    int v = (t < SCANB) ? g_bsum[t] : 0;
    s[t] = v;
    __syncthreads();
#pragma unroll
    for (int o = 1; o < 512; o <<= 1) {
        int u = (t >= o) ? s[t - o] : 0;
        __syncthreads();
        s[t] += u;
        __syncthreads();
    }
    g_boff[t] = s[t] - v;
}

__global__ void k_scanC() {
    int n = blockIdx.x * 256 + threadIdx.x;
    if (n < NN) {
        int o = g_loc[n] + g_boff[blockIdx.x];
        g_off[n] = o;
        g_cur[n] = o;
    }
    if (n == 0) g_off[NN] = EE;
}

__global__ void k_scatter(const int* __restrict__ ei) {
    int e = blockIdx.x * blockDim.x + threadIdx.x;
    int src = ei[e];
    int tgt = ei[EE + e];
    int p = atomicAdd(&g_cur[tgt], 1);
    g_sed[p] = make_int2(src, e);
}

// ---------------------------------------------------------------------------
// Kernel 2 (edge pass, round-7 structure, ZERO atomics, ZERO scatter):
// stages full fp16 rows via cp.async, computes gate + per-head exp(alpha),
// stores a4 + gate coalesced. Constants indexed warp-uniformly.
// ---------------------------------------------------------------------------
#define ETPB 128
#define RST 72

__global__ void __launch_bounds__(ETPB, 6) k_edge(
        const int* __restrict__ ei, const float* __restrict__ eag) {
    __shared__ __align__(16) __half sXL[4][32 * RST];
    __shared__ __align__(16) __half sXR[4][32 * RST];

    int t = threadIdx.x, lane = t & 31, w = t >> 5;
    __half* XL = sXL[w];
    __half* XR = sXR[w];

    int e = blockIdx.x * ETPB + t;
    int src = ei[e];
    int tgt = ei[EE + e];

    int rlane = lane >> 3;
    int off8  = (lane & 7) * 8;
#pragma unroll
    for (int i = 0; i < 8; i++) {
        int r  = i * 4 + rlane;
        int s  = __shfl_sync(0xFFFFFFFFu, src, r);
        int tg = __shfl_sync(0xFFFFFFFFu, tgt, r);
        cpa16(&XL[r * RST + off8], g_xlh + (size_t)s  * 64 + off8);
        cpa16(&XR[r * RST + off8], g_xrh + (size_t)tg * 64 + off8);
    }
    asm volatile("cp.async.commit_group;" ::: "memory");

    // ---- overlap: ea load + gate MLP ----
    float ea[16];
    {
        const float4* eap = (const float4*)(eag + (size_t)e * 16);
#pragma unroll
        for (int i = 0; i < 4; i++) {
            float4 v = eap[i];
            ea[4 * i + 0] = v.x; ea[4 * i + 1] = v.y;
            ea[4 * i + 2] = v.z; ea[4 * i + 3] = v.w;
        }
    }
    float gate;
    {
        u64 h2[16];
        const u64* bg1p = (const u64*)cbg1;
#pragma unroll
        for (int j = 0; j < 16; j++) h2[j] = bg1p[j];
        const u64* wg1p = (const u64*)cWg1;
#pragma unroll
        for (int i = 0; i < 16; i++) {
            u64 a2 = pack2(ea[i], ea[i]);
#pragma unroll
            for (int j = 0; j < 16; j++) fma2(h2[j], a2, wg1p[i * 16 + j]);
        }
        float gacc = cbg2[0];
#pragma unroll
        for (int j = 0; j < 16; j++) {
            float h0, h1; unpack2(h2[j], h0, h1);
            gacc += h0 * sigmoidf_(h0) * cWg2[2 * j] +
                    h1 * sigmoidf_(h1) * cWg2[2 * j + 1];
        }
        gate = sigmoidf_(gacc);
    }

    asm volatile("cp.async.wait_group 0;" ::: "memory");
    __syncwarp();

    // ---- per-head logits (uniform head loop) ----
    const u64* we2p = (const u64*)cWe;
    float ah[4];
#pragma unroll
    for (int h = 0; h < 4; h++) {
        uint4 l0 = *(const uint4*)&XL[lane * RST + h * 16];
        uint4 l1 = *(const uint4*)&XL[lane * RST + h * 16 + 8];
        uint4 r0 = *(const uint4*)&XR[lane * RST + h * 16];
        uint4 r1 = *(const uint4*)&XR[lane * RST + h * 16 + 8];

        u64 s2[8];
        {
            const unsigned* lw = (const unsigned*)&l0;
            const unsigned* rw = (const unsigned*)&r0;
#pragma unroll
            for (int p = 0; p < 4; p++) {
                __half2 sum = __hadd2(*(const __half2*)&lw[p], *(const __half2*)&rw[p]);
                float2 f = __half22float2(sum);
                s2[p] = pack2(f.x, f.y);
            }
            lw = (const unsigned*)&l1;
            rw = (const unsigned*)&r1;
#pragma unroll
            for (int p = 0; p < 4; p++) {
                __half2 sum = __hadd2(*(const __half2*)&lw[p], *(const __half2*)&rw[p]);
                float2 f = __half22float2(sum);
                s2[4 + p] = pack2(f.x, f.y);
            }
        }
#pragma unroll
        for (int i = 0; i < 16; i++) {
            u64 a2 = pack2(ea[i], ea[i]);
#pragma unroll
            for (int p = 0; p < 8; p++)
                fma2(s2[p], a2, we2p[i * 32 + h * 8 + p]);
        }
        float acc = 0.f;
#pragma unroll
        for (int p = 0; p < 8; p++) {
            float m0, m1; unpack2(s2[p], m0, m1);
            acc += leaky(m0) * catt[h * 16 + 2 * p] +
                   leaky(m1) * catt[h * 16 + 2 * p + 1];
        }
        ah[h] = __expf(acc);    // no max-shift: ratios invariant, range safe
    }

    g_a4[e]   = make_float4(ah[0], ah[1], ah[2], ah[3]);
    g_gate[e] = gate;
}

// ---------------------------------------------------------------------------
// Kernel 3: per-node gather (batched x4 prefetch) + softmax-normalize +
// gate-mean + LayerNorm + SiLU + residual. One warp per node, zero atomics.
// ---------------------------------------------------------------------------
__global__ void __launch_bounds__(256) k_gather(
        const float* __restrict__ x,
        const float* __restrict__ conv_bias,
        const float* __restrict__ gamma,
        const float* __restrict__ beta,
        float* __restrict__ out) {
    int n = (blockIdx.x * blockDim.x + threadIdx.x) >> 5;
    int lane = threadIdx.x & 31;
    int h = lane >> 3;                      // head for channels {2lane, 2lane+1}

    int row = g_off[n];
    int deg = g_off[n + 1] - row;

    u64 acc = pack2(0.f, 0.f);
    float den = 0.f, gsum = 0.f;

    for (int j0 = 0; j0 < deg; j0 += 4) {
        int km = deg - j0;                  // >=1
        // batch-load (independent chains; up to 16 loads in flight)
        int2 se0, se1, se2, se3;
        se0 = g_sed[row + j0];
        se1 = g_sed[row + j0 + ((km > 1) ? 1 : 0)];
        se2 = g_sed[row + j0 + ((km > 2) ? 2 : 0)];
        se3 = g_sed[row + j0 + ((km > 3) ? 3 : 0)];

        float4 a40 = g_a4[se0.y], a41 = g_a4[se1.y],
               a42 = g_a4[se2.y], a43 = g_a4[se3.y];
        float  gt0 = g_gate[se0.y], gt1 = g_gate[se1.y],
               gt2 = g_gate[se2.y], gt3 = g_gate[se3.y];
        __half2 x0 = *(const __half2*)&g_xlh[(size_t)se0.x * 64 + 2 * lane];
        __half2 x1 = *(const __half2*)&g_xlh[(size_t)se1.x * 64 + 2 * lane];
        __half2 x2 = *(const __half2*)&g_xlh[(size_t)se2.x * 64 + 2 * lane];
        __half2 x3 = *(const __half2*)&g_xlh[(size_t)se3.x * 64 + 2 * lane];

        float m1 = (km > 1) ? 1.f : 0.f;
        float m2 = (km > 2) ? 1.f : 0.f;
        float m3 = (km > 3) ? 1.f : 0.f;

        float a0 = (h == 0) ? a40.x : (h == 1) ? a40.y : (h == 2) ? a40.z : a40.w;
        float a1 = ((h == 0) ? a41.x : (h == 1) ? a41.y : (h == 2) ? a41.z : a41.w) * m1;
        float a2 = ((h == 0) ? a42.x : (h == 1) ? a42.y : (h == 2) ? a42.z : a42.w) * m2;
        float a3 = ((h == 0) ? a43.x : (h == 1) ? a43.y : (h == 2) ? a43.z : a43.w) * m3;

        float2 f0 = __half22float2(x0), f1 = __half22float2(x1);
        float2 f2 = __half22float2(x2), f3 = __half22float2(x3);
        fma2(acc, pack2(a0, a0), pack2(f0.x, f0.y));
        fma2(acc, pack2(a1, a1), pack2(f1.x, f1.y));
        fma2(acc, pack2(a2, a2), pack2(f2.x, f2.y));
        fma2(acc, pack2(a3, a3), pack2(f3.x, f3.y));
        den  += (a0 + a1) + (a2 + a3);
        gsum += gt0 + gt1 * m1 + gt2 * m2 + gt3 * m3;
    }

    float inv = den > 0.f ? 1.f / den : 0.f;
    float mg  = gsum / fmaxf((float)deg, 1.f);

    float2 cb = ((const float2*)conv_bias)[lane];
    float a0, a1; unpack2(acc, a0, a1);
    float v0 = (a0 * inv + cb.x) * mg;
    float v1 = (a1 * inv + cb.y) * mg;

    float s  = v0 + v1;
    float sq = v0 * v0 + v1 * v1;
#pragma unroll
    for (int o = 16; o > 0; o >>= 1) {
        s  += __shfl_xor_sync(0xFFFFFFFFu, s,  o);
        sq += __shfl_xor_sync(0xFFFFFFFFu, sq, o);
    }
    float mu   = s * (1.f / 64.f);
    float var  = sq * (1.f / 64.f) - mu * mu;
    float rstd = rsqrtf(var + 1e-5f);

    float2 g  = ((const float2*)gamma)[lane];
    float2 bt = ((const float2*)beta)[lane];
    float2 xv = ((const float2*)x)[(size_t)n * 32 + lane];
    float n0 = (v0 - mu) * rstd * g.x + bt.x;
    float n1 = (v1 - mu) * rstd * g.y + bt.y;
    n0 *= sigmoidf_(n0);
    n1 *= sigmoidf_(n1);
    ((float2*)out)[(size_t)n * 32 + lane] = make_float2(n0 + xv.x, n1 + xv.y);
}

// ---------------------------------------------------------------------------
extern "C" void kernel_launch(void* const* d_in, const int* in_sizes, int n_in,
                              void* d_out, int out_size) {
    const float* x         = (const float*)d_in[0];
    const int*   ei        = (const int*)  d_in[1];
    const float* edge_attr = (const float*)d_in[2];
    const float* Wl        = (const float*)d_in[3];
    const float* bl        = (const float*)d_in[4];
    const float* Wr        = (const float*)d_in[5];
    const float* br        = (const float*)d_in[6];
    const float* conv_bias = (const float*)d_in[9];
    const float* gamma     = (const float*)d_in[14];
    const float* beta      = (const float*)d_in[15];
    float* out = (float*)d_out;

    cudaMemcpyToSymbolAsync(cWe,  d_in[7],  1024 * 4, 0, cudaMemcpyDeviceToDevice, 0);
    cudaMemcpyToSymbolAsync(catt, d_in[8],  64 * 4,   0, cudaMemcpyDeviceToDevice, 0);
    cudaMemcpyToSymbolAsync(cWg1, d_in[10], 512 * 4,  0, cudaMemcpyDeviceToDevice, 0);
    cudaMemcpyToSymbolAsync(cbg1, d_in[11], 32 * 4,   0, cudaMemcpyDeviceToDevice, 0);
    cudaMemcpyToSymbolAsync(cWg2, d_in[12], 32 * 4,   0, cudaMemcpyDeviceToDevice, 0);
    cudaMemcpyToSymbolAsync(cbg2, d_in[13], 4,        0, cudaMemcpyDeviceToDevice, 0);

    k_prep   <<<(NN + 63) / 64, 256>>>(x, Wl, bl, Wr, br);
    k_hist   <<<EE / 256, 256>>>(ei);
    k_scanA  <<<SCANB, 256>>>();
    k_scanB  <<<1, 512>>>();
    k_scanC  <<<SCANB, 256>>>();
    k_scatter<<<EE / 256, 256>>>(ei);
    k_edge   <<<EE / ETPB, ETPB>>>(ei, edge_attr);
    k_gather <<<NN * 32 / 256, 256>>>(x, conv_bias, gamma, beta, out);
}

// round 11
// speedup vs baseline: 11.3665x; 1.1657x over previous
#include <cuda_runtime.h>
#include <cuda_fp16.h>

#define NN 100000
#define EE 1600000
#define TPB 256

typedef unsigned long long u64;

// ---- scratch (__device__ globals; no allocations allowed) ----
__device__ __half   g_xlh[NN * 64];   // fp16 x @ Wl + bl (logits + messages)
__device__ __half   g_xrh[NN * 64];   // fp16 x @ Wr + br (logits only)
__device__ float4   g_denom[NN];      // per-head softmax denominators
__device__ float2   g_gate2[NN];      // {gate_sum, degree} per target

// ---- small params in constant memory (warp-uniform indexing only) ----
__constant__ __align__(16) float cWe[1024];   // [16,64]
__constant__ __align__(16) float cWg1[512];   // [16,32]
__constant__ __align__(16) float cWg2[32];
__constant__ __align__(16) float cbg1[32];
__constant__ __align__(16) float catt[64];
__constant__ __align__(16) float cbias[64];
__constant__ __align__(16) float cgamma[64];
__constant__ __align__(16) float cbeta[64];
__constant__ float cbg2[1];

__device__ __forceinline__ float sigmoidf_(float v) {
    return 1.f / (1.f + __expf(-v));
}
__device__ __forceinline__ u64 pack2(float lo, float hi) {
    u64 r; asm("mov.b64 %0, {%1,%2};" : "=l"(r) : "f"(lo), "f"(hi)); return r;
}
__device__ __forceinline__ void unpack2(u64 v, float& lo, float& hi) {
    asm("mov.b64 {%0,%1}, %2;" : "=f"(lo), "=f"(hi) : "l"(v));
}
__device__ __forceinline__ void fma2(u64& d, u64 a, u64 b) {
    asm("fma.rn.f32x2 %0, %1, %2, %0;" : "+l"(d) : "l"(a), "l"(b));
}
__device__ __forceinline__ void red4(float* p, float a, float b, float c, float d) {
    asm volatile("red.global.add.v4.f32 [%0], {%1,%2,%3,%4};"
                 :: "l"(p), "f"(a), "f"(b), "f"(c), "f"(d) : "memory");
}
__device__ __forceinline__ void red2(float* p, float a, float b) {
    asm volatile("red.global.add.v2.f32 [%0], {%1,%2};"
                 :: "l"(p), "f"(a), "f"(b) : "memory");
}
__device__ __forceinline__ float leaky(float m) { return fmaxf(m, 0.2f * m); }
__device__ __forceinline__ void cpa16(__half* smem_dst, const __half* gsrc) {
    unsigned d = (unsigned)__cvta_generic_to_shared(smem_dst);
    asm volatile("cp.async.ca.shared.global [%0], [%1], 16;"
                 :: "r"(d), "l"(gsrc) : "memory");
}
__device__ __forceinline__ unsigned h2_bits(__half2 v) {
    return *reinterpret_cast<unsigned*>(&v);
}

// ---------------------------------------------------------------------------
// Kernel 1: node transforms (fp16 out) + init accumulators + zero d_out.
// (round-3/7 structure, measured ~42us)
// ---------------------------------------------------------------------------
__global__ void __launch_bounds__(256) k_prep(
        const float* __restrict__ x,
        const float* __restrict__ Wl, const float* __restrict__ bl,
        const float* __restrict__ Wr, const float* __restrict__ br,
        float* __restrict__ out) {
    __shared__ __align__(16) float Ws[64 * 128];
    __shared__ __align__(16) float xs[64 * 64];
    int t = threadIdx.x;
    int nb = blockIdx.x * 64;

#pragma unroll
    for (int i = 0; i < 16; i++) {
        int idx = t + i * 256;
        int k = idx >> 6, c = idx & 63;
        Ws[k * 128 + c]      = Wl[idx];
        Ws[k * 128 + 64 + c] = Wr[idx];
    }
#pragma unroll
    for (int i = 0; i < 16; i++) {
        int idx = t + i * 256;
        int n = nb + (idx >> 6);
        bool ok = n < NN;
        xs[idx] = ok ? x[(size_t)n * 64 + (idx & 63)] : 0.f;
        if (ok) out[(size_t)n * 64 + (idx & 63)] = 0.f;
    }
    if (t < 64) {
        int n = nb + t;
        if (n < NN) {
            g_denom[n] = make_float4(0.f, 0.f, 0.f, 0.f);
            g_gate2[n] = make_float2(0.f, 0.f);
        }
    }
    __syncthreads();

    int cg = t & 31, ng = t >> 5;
    int c0 = cg * 4;
    const float* bsrc = (c0 < 64) ? (bl + c0) : (br + (c0 - 64));
    float4 bias = *(const float4*)bsrc;

    u64 acc[8][2];
#pragma unroll
    for (int j = 0; j < 8; j++) {
        acc[j][0] = pack2(bias.x, bias.y);
        acc[j][1] = pack2(bias.z, bias.w);
    }

    for (int k4 = 0; k4 < 16; k4++) {
        float4 xv[8];
#pragma unroll
        for (int j = 0; j < 8; j++)
            xv[j] = *(const float4*)&xs[(ng * 8 + j) * 64 + k4 * 4];
#pragma unroll
        for (int kk = 0; kk < 4; kk++) {
            float4 wv = *(const float4*)&Ws[(k4 * 4 + kk) * 128 + c0];
            u64 w01 = pack2(wv.x, wv.y), w23 = pack2(wv.z, wv.w);
#pragma unroll
            for (int j = 0; j < 8; j++) {
                float xsc = (kk == 0) ? xv[j].x : (kk == 1) ? xv[j].y
                          : (kk == 2) ? xv[j].z : xv[j].w;
                u64 xx = pack2(xsc, xsc);
                fma2(acc[j][0], xx, w01);
                fma2(acc[j][1], xx, w23);
            }
        }
    }

    __half* dsth = (c0 < 64) ? g_xlh : g_xrh;
    int cc = c0 & 63;
#pragma unroll
    for (int j = 0; j < 8; j++) {
        int n = nb + ng * 8 + j;
        if (n < NN) {
            float o0, o1, o2, o3;
            unpack2(acc[j][0], o0, o1);
            unpack2(acc[j][1], o2, o3);
            uint2 p;
            p.x = h2_bits(__floats2half2_rn(o0, o1));
            p.y = h2_bits(__floats2half2_rn(o2, o3));
            *(uint2*)&dsth[(size_t)n * 64 + cc] = p;
        }
    }
}

// ---------------------------------------------------------------------------
// Kernel 2 (fused edge pass, round-7 structure, spill-free):
//  - NO min-blocks clause: ptxas gets full register budget (no LDL/STL)
//  - gate MLP in 2 passes of 8 u64 accumulators (halves live regs)
//  - full fp16 row staging via cp.async, per-head logits, message scatter
// ---------------------------------------------------------------------------
#define ETPB 128
#define RST 72                              // halfs per staged row (64 + 8 pad)

__global__ void __launch_bounds__(ETPB) k_edge(
        const int* __restrict__ ei, const float* __restrict__ eag,
        float* __restrict__ out) {
    __shared__ __align__(16) __half sXL[4][32 * RST];
    __shared__ __align__(16) __half sXR[4][32 * RST];
    __shared__ __align__(16) float  sMeta[4][32][8];

    int t = threadIdx.x, lane = t & 31, w = t >> 5;
    __half* XL = sXL[w];
    __half* XR = sXR[w];
    float (*meta)[8] = sMeta[w];

    int e = blockIdx.x * ETPB + t;          // EE % ETPB == 0
    int src = ei[e];
    int tgt = ei[EE + e];

    // ---- phase A: stage full fp16 rows (4 rows / 1 line each per instr) ----
    int rlane = lane >> 3;
    int off8  = (lane & 7) * 8;
#pragma unroll
    for (int i = 0; i < 8; i++) {
        int r  = i * 4 + rlane;
        int s  = __shfl_sync(0xFFFFFFFFu, src, r);
        int tg = __shfl_sync(0xFFFFFFFFu, tgt, r);
        cpa16(&XL[r * RST + off8], g_xlh + (size_t)s  * 64 + off8);
        cpa16(&XR[r * RST + off8], g_xrh + (size_t)tg * 64 + off8);
    }
    asm volatile("cp.async.commit_group;" ::: "memory");

    // ---- overlap: ea load + gate MLP (2 passes of 8 hidden-unit pairs) ----
    float ea[16];
    {
        const float4* eap = (const float4*)(eag + (size_t)e * 16);
#pragma unroll
        for (int i = 0; i < 4; i++) {
            float4 v = eap[i];
            ea[4 * i + 0] = v.x; ea[4 * i + 1] = v.y;
            ea[4 * i + 2] = v.z; ea[4 * i + 3] = v.w;
        }
    }
    float gacc = cbg2[0];
#pragma unroll
    for (int half = 0; half < 2; half++) {
        u64 h2[8];
        const u64* bg1p = (const u64*)cbg1;
#pragma unroll
        for (int j = 0; j < 8; j++) h2[j] = bg1p[half * 8 + j];
        const u64* wg1p = (const u64*)cWg1;
#pragma unroll
        for (int i = 0; i < 16; i++) {
            u64 a2 = pack2(ea[i], ea[i]);
#pragma unroll
            for (int j = 0; j < 8; j++)
                fma2(h2[j], a2, wg1p[i * 16 + half * 8 + j]);
        }
#pragma unroll
        for (int j = 0; j < 8; j++) {
            float h0, h1; unpack2(h2[j], h0, h1);
            gacc += h0 * sigmoidf_(h0) * cWg2[half * 16 + 2 * j] +
                    h1 * sigmoidf_(h1) * cWg2[half * 16 + 2 * j + 1];
        }
    }
    red2((float*)&g_gate2[tgt], sigmoidf_(gacc), 1.f);

    asm volatile("cp.async.wait_group 0;" ::: "memory");
    __syncwarp();

    // ---- phase B: per-head logits from staged fp16 rows ----
    const u64* we2p = (const u64*)cWe;
    float ah[4];
#pragma unroll
    for (int h = 0; h < 4; h++) {
        uint4 l0 = *(const uint4*)&XL[lane * RST + h * 16];
        uint4 l1 = *(const uint4*)&XL[lane * RST + h * 16 + 8];
        uint4 r0 = *(const uint4*)&XR[lane * RST + h * 16];
        uint4 r1 = *(const uint4*)&XR[lane * RST + h * 16 + 8];

        u64 s2[8];
        {
            const unsigned* lw = (const unsigned*)&l0;
            const unsigned* rw = (const unsigned*)&r0;
#pragma unroll
            for (int p = 0; p < 4; p++) {
                __half2 sum = __hadd2(*(const __half2*)&lw[p], *(const __half2*)&rw[p]);
                float2 f = __half22float2(sum);
                s2[p] = pack2(f.x, f.y);
            }
            lw = (const unsigned*)&l1;
            rw = (const unsigned*)&r1;
#pragma unroll
            for (int p = 0; p < 4; p++) {
                __half2 sum = __hadd2(*(const __half2*)&lw[p], *(const __half2*)&rw[p]);
                float2 f = __half22float2(sum);
                s2[4 + p] = pack2(f.x, f.y);
            }
        }
#pragma unroll
        for (int i = 0; i < 16; i++) {
            u64 a2 = pack2(ea[i], ea[i]);
#pragma unroll
            for (int p = 0; p < 8; p++)
                fma2(s2[p], a2, we2p[i * 32 + h * 8 + p]);
        }
        float acc = 0.f;
#pragma unroll
        for (int p = 0; p < 8; p++) {
            float m0, m1; unpack2(s2[p], m0, m1);
            acc += leaky(m0) * catt[h * 16 + 2 * p] +
                   leaky(m1) * catt[h * 16 + 2 * p + 1];
        }
        ah[h] = __expf(acc);   // no max-shift: ratios invariant, range safe
    }

    *(float4*)&meta[lane][0] = make_float4(ah[0], ah[1], ah[2], ah[3]);
    meta[lane][4] = __int_as_float(tgt);
    red4((float*)&g_denom[tgt], ah[0], ah[1], ah[2], ah[3]);
    __syncwarp();

    // ---- phase C: messages from staged fp16 xl, cooperative red4 scatter ----
    int q    = lane & 15;                 // 16 lanes cover a 64-float out row
    int rsel = lane >> 4;                 // 2 rows per iteration
    int h_c  = q >> 2;                    // head owning this 16B out chunk
#pragma unroll
    for (int i = 0; i < 16; i++) {
        int r   = 2 * i + rsel;
        float a = meta[r][h_c];
        int tg  = __float_as_int(meta[r][4]);
        uint2 hv = *(const uint2*)&XL[r * RST + q * 4];
        float2 f01 = __half22float2(*(const __half2*)&hv.x);
        float2 f23 = __half22float2(*(const __half2*)&hv.y);
        red4(out + (size_t)tg * 64 + q * 4,
             f01.x * a, f01.y * a, f23.x * a, f23.y * a);
    }
}

// ---------------------------------------------------------------------------
// Kernel 3: node epilogue — 16 threads/node, float4 lanes, constant params.
// ---------------------------------------------------------------------------
__global__ void k_final(const float* __restrict__ x, float* __restrict__ out) {
    int gid = blockIdx.x * blockDim.x + threadIdx.x;
    int n = gid >> 4;
    int q = threadIdx.x & 15;
    int h = q >> 2;

    float2 gd = g_gate2[n];
    float mg = gd.x / fmaxf(gd.y, 1.f);
    float4 den4 = g_denom[n];
    float den = (h == 0) ? den4.x : (h == 1) ? den4.y : (h == 2) ? den4.z : den4.w;
    float inv = den > 0.f ? 1.f / den : 0.f;

    size_t idx = (size_t)n * 16 + q;
    float4 o  = ((const float4*)out)[idx];
    float4 cb = ((const float4*)cbias)[q];
    float4 v;
    v.x = (o.x * inv + cb.x) * mg;
    v.y = (o.y * inv + cb.y) * mg;
    v.z = (o.z * inv + cb.z) * mg;
    v.w = (o.w * inv + cb.w) * mg;

    float s  = v.x + v.y + v.z + v.w;
    float sq = v.x * v.x + v.y * v.y + v.z * v.z + v.w * v.w;
#pragma unroll
    for (int ofs = 1; ofs < 16; ofs <<= 1) {
        s  += __shfl_xor_sync(0xFFFFFFFFu, s,  ofs);
        sq += __shfl_xor_sync(0xFFFFFFFFu, sq, ofs);
    }
    float mu   = s * (1.f / 64.f);
    float var  = sq * (1.f / 64.f) - mu * mu;
    float rstd = rsqrtf(var + 1e-5f);

    float4 g  = ((const float4*)cgamma)[q];
    float4 bt = ((const float4*)cbeta)[q];
    float4 xv = ((const float4*)x)[idx];
    float4 r;
    float n0 = (v.x - mu) * rstd * g.x + bt.x;  n0 *= sigmoidf_(n0);  r.x = n0 + xv.x;
    float n1 = (v.y - mu) * rstd * g.y + bt.y;  n1 *= sigmoidf_(n1);  r.y = n1 + xv.y;
    float n2 = (v.z - mu) * rstd * g.z + bt.z;  n2 *= sigmoidf_(n2);  r.z = n2 + xv.z;
    float n3 = (v.w - mu) * rstd * g.w + bt.w;  n3 *= sigmoidf_(n3);  r.w = n3 + xv.w;
    ((float4*)out)[idx] = r;
}

// ---------------------------------------------------------------------------
extern "C" void kernel_launch(void* const* d_in, const int* in_sizes, int n_in,
                              void* d_out, int out_size) {
    const float* x         = (const float*)d_in[0];
    const int*   ei        = (const int*)  d_in[1];
    const float* edge_attr = (const float*)d_in[2];
    const float* Wl        = (const float*)d_in[3];
    const float* bl        = (const float*)d_in[4];
    const float* Wr        = (const float*)d_in[5];
    const float* br        = (const float*)d_in[6];
    float* out = (float*)d_out;

    cudaMemcpyToSymbolAsync(cWe,    d_in[7],  1024 * 4, 0, cudaMemcpyDeviceToDevice, 0);
    cudaMemcpyToSymbolAsync(catt,   d_in[8],  64 * 4,   0, cudaMemcpyDeviceToDevice, 0);
    cudaMemcpyToSymbolAsync(cbias,  d_in[9],  64 * 4,   0, cudaMemcpyDeviceToDevice, 0);
    cudaMemcpyToSymbolAsync(cWg1,   d_in[10], 512 * 4,  0, cudaMemcpyDeviceToDevice, 0);
    cudaMemcpyToSymbolAsync(cbg1,   d_in[11], 32 * 4,   0, cudaMemcpyDeviceToDevice, 0);
    cudaMemcpyToSymbolAsync(cWg2,   d_in[12], 32 * 4,   0, cudaMemcpyDeviceToDevice, 0);
    cudaMemcpyToSymbolAsync(cbg2,   d_in[13], 4,        0, cudaMemcpyDeviceToDevice, 0);
    cudaMemcpyToSymbolAsync(cgamma, d_in[14], 64 * 4,   0, cudaMemcpyDeviceToDevice, 0);
    cudaMemcpyToSymbolAsync(cbeta,  d_in[15], 64 * 4,   0, cudaMemcpyDeviceToDevice, 0);

    k_prep <<<(NN + 63) / 64, 256>>>(x, Wl, bl, Wr, br, out);
    k_edge <<<EE / ETPB, ETPB>>>(ei, edge_attr, out);
    k_final<<<NN * 16 / TPB, TPB>>>(x, out);
}

// round 12
// speedup vs baseline: 13.5696x; 1.1938x over previous
#include <cuda_runtime.h>
#include <cuda_fp16.h>

#define NN 100000
#define EE 1600000
#define TPB 256

typedef unsigned long long u64;
typedef unsigned int u32;

// ---- scratch (__device__ globals; no allocations allowed) ----
__device__ __half   g_xlh[NN * 64];   // fp16 x @ Wl + bl (logits + messages)
__device__ __half   g_xrh[NN * 64];   // fp16 x @ Wr + br (logits only)
__device__ float4   g_denom[NN];      // per-head softmax denominators
__device__ float2   g_gate2[NN];      // {gate_sum, degree} per target
__device__ __half   g_Wt[96 * 16];    // transposed fp16 [We | Wg1]: Wt[c][k]

__device__ __forceinline__ float sigmoidf_(float v) {
    return 1.f / (1.f + __expf(-v));
}
__device__ __forceinline__ u64 pack2(float lo, float hi) {
    u64 r; asm("mov.b64 %0, {%1,%2};" : "=l"(r) : "f"(lo), "f"(hi)); return r;
}
__device__ __forceinline__ void unpack2(u64 v, float& lo, float& hi) {
    asm("mov.b64 {%0,%1}, %2;" : "=f"(lo), "=f"(hi) : "l"(v));
}
__device__ __forceinline__ void fma2(u64& d, u64 a, u64 b) {
    asm("fma.rn.f32x2 %0, %1, %2, %0;" : "+l"(d) : "l"(a), "l"(b));
}
__device__ __forceinline__ void red4(float* p, float a, float b, float c, float d) {
    asm volatile("red.global.add.v4.f32 [%0], {%1,%2,%3,%4};"
                 :: "l"(p), "f"(a), "f"(b), "f"(c), "f"(d) : "memory");
}
__device__ __forceinline__ void red2(float* p, float a, float b) {
    asm volatile("red.global.add.v2.f32 [%0], {%1,%2};"
                 :: "l"(p), "f"(a), "f"(b) : "memory");
}
__device__ __forceinline__ float leaky(float m) { return fmaxf(m, 0.2f * m); }
__device__ __forceinline__ void cpa16(__half* smem_dst, const __half* gsrc) {
    unsigned d = (unsigned)__cvta_generic_to_shared(smem_dst);
    asm volatile("cp.async.ca.shared.global [%0], [%1], 16;"
                 :: "r"(d), "l"(gsrc) : "memory");
}
__device__ __forceinline__ unsigned h2_bits(__half2 v) {
    return *reinterpret_cast<unsigned*>(&v);
}
// m16n8k16 row.col f16f16 -> f32, D==C accumulate in place
__device__ __forceinline__ void mma16816(float& d0, float& d1, float& d2, float& d3,
                                         u32 a0, u32 a1, u32 a2, u32 a3,
                                         u32 b0, u32 b1) {
    asm volatile(
        "mma.sync.aligned.m16n8k16.row.col.f32.f16.f16.f32 "
        "{%0,%1,%2,%3}, {%4,%5,%6,%7}, {%8,%9}, {%0,%1,%2,%3};"
        : "+f"(d0), "+f"(d1), "+f"(d2), "+f"(d3)
        : "r"(a0), "r"(a1), "r"(a2), "r"(a3), "r"(b0), "r"(b1));
}

// ---------------------------------------------------------------------------
// Kernel 0: build transposed fp16 weight matrix Wt[96][16] = [We | Wg1]^T
// ---------------------------------------------------------------------------
__global__ void k_wcvt(const float* __restrict__ We, const float* __restrict__ Wg1) {
    int i = blockIdx.x * blockDim.x + threadIdx.x;    // 1536 elements
    if (i < 96 * 16) {
        int c = i >> 4, k = i & 15;
        float v = (c < 64) ? We[k * 64 + c] : Wg1[k * 32 + (c - 64)];
        g_Wt[i] = __float2half_rn(v);
    }
}

// ---------------------------------------------------------------------------
// Kernel 1: node transforms (fp16 out) + init accumulators + zero d_out.
// ---------------------------------------------------------------------------
__global__ void __launch_bounds__(256) k_prep(
        const float* __restrict__ x,
        const float* __restrict__ Wl, const float* __restrict__ bl,
        const float* __restrict__ Wr, const float* __restrict__ br,
        float* __restrict__ out) {
    __shared__ __align__(16) float Ws[64 * 128];
    __shared__ __align__(16) float xs[64 * 64];
    int t = threadIdx.x;
    int nb = blockIdx.x * 64;

#pragma unroll
    for (int i = 0; i < 16; i++) {
        int idx = t + i * 256;
        int k = idx >> 6, c = idx & 63;
        Ws[k * 128 + c]      = Wl[idx];
        Ws[k * 128 + 64 + c] = Wr[idx];
    }
#pragma unroll
    for (int i = 0; i < 16; i++) {
        int idx = t + i * 256;
        int n = nb + (idx >> 6);
        bool ok = n < NN;
        xs[idx] = ok ? x[(size_t)n * 64 + (idx & 63)] : 0.f;
        if (ok) out[(size_t)n * 64 + (idx & 63)] = 0.f;
    }
    if (t < 64) {
        int n = nb + t;
        if (n < NN) {
            g_denom[n] = make_float4(0.f, 0.f, 0.f, 0.f);
            g_gate2[n] = make_float2(0.f, 0.f);
        }
    }
    __syncthreads();

    int cg = t & 31, ng = t >> 5;
    int c0 = cg * 4;
    const float* bsrc = (c0 < 64) ? (bl + c0) : (br + (c0 - 64));
    float4 bias = *(const float4*)bsrc;

    u64 acc[8][2];
#pragma unroll
    for (int j = 0; j < 8; j++) {
        acc[j][0] = pack2(bias.x, bias.y);
        acc[j][1] = pack2(bias.z, bias.w);
    }

    for (int k4 = 0; k4 < 16; k4++) {
        float4 xv[8];
#pragma unroll
        for (int j = 0; j < 8; j++)
            xv[j] = *(const float4*)&xs[(ng * 8 + j) * 64 + k4 * 4];
#pragma unroll
        for (int kk = 0; kk < 4; kk++) {
            float4 wv = *(const float4*)&Ws[(k4 * 4 + kk) * 128 + c0];
            u64 w01 = pack2(wv.x, wv.y), w23 = pack2(wv.z, wv.w);
#pragma unroll
            for (int j = 0; j < 8; j++) {
                float xsc = (kk == 0) ? xv[j].x : (kk == 1) ? xv[j].y
                          : (kk == 2) ? xv[j].z : xv[j].w;
                u64 xx = pack2(xsc, xsc);
                fma2(acc[j][0], xx, w01);
                fma2(acc[j][1], xx, w23);
            }
        }
    }

    __half* dsth = (c0 < 64) ? g_xlh : g_xrh;
    int cc = c0 & 63;
#pragma unroll
    for (int j = 0; j < 8; j++) {
        int n = nb + ng * 8 + j;
        if (n < NN) {
            float o0, o1, o2, o3;
            unpack2(acc[j][0], o0, o1);
            unpack2(acc[j][1], o2, o3);
            uint2 p;
            p.x = h2_bits(__floats2half2_rn(o0, o1));
            p.y = h2_bits(__floats2half2_rn(o2, o3));
            *(uint2*)&dsth[(size_t)n * 64 + cc] = p;
        }
    }
}

// ---------------------------------------------------------------------------
// Kernel 2 (fused edge pass, TENSOR-CORE matmuls):
//   Per warp: 32 edges. C[32,96] = ea[32,16] @ [We|Wg1][16,96] via 24x
//   mma.sync.m16n8k16 (fp16 in, fp32 acc). Scalar epilogue does
//   +xl+xr, leaky, att-dot (heads), SiLU/Wg2 (gate), exp, quad-reduce.
//   Messages scattered from staged fp16 xl rows (phase C, as R7).
// ---------------------------------------------------------------------------
#define ETPB 128
#define RST 72                              // halfs per staged row (64 + 8 pad)
#define EAST 24                             // halfs per ea row (16 + 8 pad)

__global__ void __launch_bounds__(ETPB) k_edge(
        const int* __restrict__ ei, const float* __restrict__ eag,
        const float* __restrict__ att, const float* __restrict__ Wg2,
        const float* __restrict__ bg1, const float* __restrict__ bg2p,
        float* __restrict__ out) {
    __shared__ __align__(16) __half sXL[4][32 * RST];
    __shared__ __align__(16) __half sXR[4][32 * RST];   // meta reuses this later
    __shared__ __align__(16) __half sEA[4][32 * EAST];
    __shared__ __align__(16) __half sWt[96 * 16];
    __shared__ __align__(16) float  sAtt[64];
    __shared__ __align__(8)  float  sWg2[32];
    __shared__ __align__(8)  float  sBg1[32];

    int t = threadIdx.x, lane = t & 31, w = t >> 5;
    __half* XL = sXL[w];
    __half* XR = sXR[w];
    __half* EA = sEA[w];

    // block-wide: stage weights (cp.async) + small params (LDG->STS)
    for (int i = t; i < 192; i += ETPB)
        cpa16(&sWt[i * 8], &g_Wt[i * 8]);
    if (t < 64) sAtt[t] = att[t];
    if (t >= 64 && t < 96)  sWg2[t - 64] = Wg2[t - 64];
    if (t >= 96 && t < 128) sBg1[t - 96] = bg1[t - 96];

    int e = blockIdx.x * ETPB + t;          // EE % ETPB == 0
    int src = ei[e];
    int tgt = ei[EE + e];

    // per-warp: stage full fp16 xl/xr rows (cp.async, 4 rows/line per instr)
    int rlane = lane >> 3;
    int off8  = (lane & 7) * 8;
#pragma unroll
    for (int i = 0; i < 8; i++) {
        int r  = i * 4 + rlane;
        int s  = __shfl_sync(0xFFFFFFFFu, src, r);
        int tg = __shfl_sync(0xFFFFFFFFu, tgt, r);
        cpa16(&XL[r * RST + off8], g_xlh + (size_t)s  * 64 + off8);
        cpa16(&XR[r * RST + off8], g_xrh + (size_t)tg * 64 + off8);
    }
    asm volatile("cp.async.commit_group;" ::: "memory");

    // stage ea as fp16 [32][24] (own row; 16B-aligned stride)
    {
        const float4* eap = (const float4*)(eag + (size_t)e * 16);
        float4 v0 = eap[0], v1 = eap[1], v2 = eap[2], v3 = eap[3];
        uint4 p0, p1;
        p0.x = h2_bits(__floats2half2_rn(v0.x, v0.y));
        p0.y = h2_bits(__floats2half2_rn(v0.z, v0.w));
        p0.z = h2_bits(__floats2half2_rn(v1.x, v1.y));
        p0.w = h2_bits(__floats2half2_rn(v1.z, v1.w));
        p1.x = h2_bits(__floats2half2_rn(v2.x, v2.y));
        p1.y = h2_bits(__floats2half2_rn(v2.z, v2.w));
        p1.z = h2_bits(__floats2half2_rn(v3.x, v3.y));
        p1.w = h2_bits(__floats2half2_rn(v3.z, v3.w));
        *(uint4*)&EA[lane * EAST]     = p0;
        *(uint4*)&EA[lane * EAST + 8] = p1;
    }
    float bg2v = bg2p[0];

    asm volatile("cp.async.wait_group 0;" ::: "memory");
    __syncthreads();                         // sWt from other threads + smem RAW

    int gr = lane >> 2;                      // group row (0..7)
    int q  = lane & 3;                       // thread in group (0..3)

    // ---- A fragments: two m-tiles (edges 0-15, 16-31) ----
    u32 a0m0 = *(const u32*)&EA[gr * EAST + 2 * q];
    u32 a1m0 = *(const u32*)&EA[(gr + 8) * EAST + 2 * q];
    u32 a2m0 = *(const u32*)&EA[gr * EAST + 2 * q + 8];
    u32 a3m0 = *(const u32*)&EA[(gr + 8) * EAST + 2 * q + 8];
    u32 a0m1 = *(const u32*)&EA[(gr + 16) * EAST + 2 * q];
    u32 a1m1 = *(const u32*)&EA[(gr + 24) * EAST + 2 * q];
    u32 a2m1 = *(const u32*)&EA[(gr + 16) * EAST + 2 * q + 8];
    u32 a3m1 = *(const u32*)&EA[(gr + 24) * EAST + 2 * q + 8];

    float ap[4][4] = {};                     // alpha partials [row-slot][head]
    float gp[4]    = {0.f, 0.f, 0.f, 0.f};   // gate partials per row-slot

#pragma unroll
    for (int nt = 0; nt < 12; nt++) {
        // B fragment: col = 8*nt + gr, k pairs 2q / 2q+8
        u32 b0 = *(const u32*)&sWt[(8 * nt + gr) * 16 + 2 * q];
        u32 b1 = *(const u32*)&sWt[(8 * nt + gr) * 16 + 2 * q + 8];

#pragma unroll
        for (int mt = 0; mt < 2; mt++) {
            float d0 = 0.f, d1 = 0.f, d2 = 0.f, d3 = 0.f;
            if (mt == 0) mma16816(d0, d1, d2, d3, a0m0, a1m0, a2m0, a3m0, b0, b1);
            else         mma16816(d0, d1, d2, d3, a0m1, a1m1, a2m1, a3m1, b0, b1);

            int r0 = gr + 16 * mt;           // rows r0 (d0,d1) and r0+8 (d2,d3)
            if (nt < 8) {                    // ---- attention head nt>>1 ----
                int col = 8 * nt + 2 * q;
                int h   = nt >> 1;
                float2 attv = *(const float2*)&sAtt[col];
                // row r0
                __half2 xl2 = *(const __half2*)&XL[r0 * RST + col];
                __half2 xr2 = *(const __half2*)&XR[r0 * RST + col];
                float2 f = __half22float2(__hadd2(xl2, xr2));
                float m0 = d0 + f.x, m1 = d1 + f.y;
                ap[2 * mt][h] += leaky(m0) * attv.x + leaky(m1) * attv.y;
                // row r0+8
                xl2 = *(const __half2*)&XL[(r0 + 8) * RST + col];
                xr2 = *(const __half2*)&XR[(r0 + 8) * RST + col];
                f = __half22float2(__hadd2(xl2, xr2));
                m0 = d2 + f.x; m1 = d3 + f.y;
                ap[2 * mt + 1][h] += leaky(m0) * attv.x + leaky(m1) * attv.y;
            } else {                         // ---- gate hidden units ----
                int hc = 8 * (nt - 8) + 2 * q;
                float2 b1v = *(const float2*)&sBg1[hc];
                float2 w2v = *(const float2*)&sWg2[hc];
                float h0 = d0 + b1v.x, h1 = d1 + b1v.y;
                gp[2 * mt]     += h0 * sigmoidf_(h0) * w2v.x +
                                  h1 * sigmoidf_(h1) * w2v.y;
                h0 = d2 + b1v.x; h1 = d3 + b1v.y;
                gp[2 * mt + 1] += h0 * sigmoidf_(h0) * w2v.x +
                                  h1 * sigmoidf_(h1) * w2v.y;
            }
        }
    }

    // ---- quad reductions (lanes sharing gr) ----
#pragma unroll
    for (int s = 0; s < 4; s++) {
#pragma unroll
        for (int h = 0; h < 4; h++) {
            ap[s][h] += __shfl_xor_sync(0xFFFFFFFFu, ap[s][h], 1);
            ap[s][h] += __shfl_xor_sync(0xFFFFFFFFu, ap[s][h], 2);
        }
        gp[s] += __shfl_xor_sync(0xFFFFFFFFu, gp[s], 1);
        gp[s] += __shfl_xor_sync(0xFFFFFFFFu, gp[s], 2);
    }

    // lane q of each quad finalizes row r = gr + 8q
    int r = gr + 8 * q;
    float e0 = __expf(ap[q][0]);
    float e1 = __expf(ap[q][1]);
    float e2 = __expf(ap[q][2]);
    float e3 = __expf(ap[q][3]);
    float gate = sigmoidf_(gp[q] + bg2v);
    int tgt_r = __shfl_sync(0xFFFFFFFFu, tgt, r);

    __syncwarp();                            // XR reads done -> reuse as meta
    float* mw = (float*)XR;                  // meta [32][8] floats
    mw[r * 8 + 0] = e0; mw[r * 8 + 1] = e1;
    mw[r * 8 + 2] = e2; mw[r * 8 + 3] = e3;
    mw[r * 8 + 4] = __int_as_float(tgt_r);
    red4((float*)&g_denom[tgt_r], e0, e1, e2, e3);
    red2((float*)&g_gate2[tgt_r], gate, 1.f);
    __syncwarp();

    // ---- phase C: messages from staged fp16 xl, cooperative red4 scatter ----
    int q15  = lane & 15;
    int rsel = lane >> 4;
    int h_c  = q15 >> 2;
#pragma unroll
    for (int i = 0; i < 16; i++) {
        int rr   = 2 * i + rsel;
        float a  = mw[rr * 8 + h_c];
        int tg   = __float_as_int(mw[rr * 8 + 4]);
        uint2 hv = *(const uint2*)&XL[rr * RST + q15 * 4];
        float2 f01 = __half22float2(*(const __half2*)&hv.x);
        float2 f23 = __half22float2(*(const __half2*)&hv.y);
        red4(out + (size_t)tg * 64 + q15 * 4,
             f01.x * a, f01.y * a, f23.x * a, f23.y * a);
    }
}

// ---------------------------------------------------------------------------
// Kernel 3: node epilogue — 16 threads/node, float4 lanes, GLOBAL params
// (coalesced LDG; avoids divergent constant-memory access).
// ---------------------------------------------------------------------------
__global__ void k_final(const float* __restrict__ x,
                        const float* __restrict__ conv_bias,
                        const float* __restrict__ gamma,
                        const float* __restrict__ beta,
                        float* __restrict__ out) {
    int gid = blockIdx.x * blockDim.x + threadIdx.x;
    int n = gid >> 4;
    int q = threadIdx.x & 15;
    int h = q >> 2;

    float2 gd = g_gate2[n];
    float mg = gd.x / fmaxf(gd.y, 1.f);
    float4 den4 = g_denom[n];
    float den = (h == 0) ? den4.x : (h == 1) ? den4.y : (h == 2) ? den4.z : den4.w;
    float inv = den > 0.f ? 1.f / den : 0.f;

    size_t idx = (size_t)n * 16 + q;
    float4 o  = ((const float4*)out)[idx];
    float4 cb = __ldg(&((const float4*)conv_bias)[q]);
    float4 v;
    v.x = (o.x * inv + cb.x) * mg;
    v.y = (o.y * inv + cb.y) * mg;
    v.z = (o.z * inv + cb.z) * mg;
    v.w = (o.w * inv + cb.w) * mg;

    float s  = v.x + v.y + v.z + v.w;
    float sq = v.x * v.x + v.y * v.y + v.z * v.z + v.w * v.w;
#pragma unroll
    for (int ofs = 1; ofs < 16; ofs <<= 1) {
        s  += __shfl_xor_sync(0xFFFFFFFFu, s,  ofs);
        sq += __shfl_xor_sync(0xFFFFFFFFu, sq, ofs);
    }
    float mu   = s * (1.f / 64.f);
    float var  = sq * (1.f / 64.f) - mu * mu;
    float rstd = rsqrtf(var + 1e-5f);

    float4 g  = __ldg(&((const float4*)gamma)[q]);
    float4 bt = __ldg(&((const float4*)beta)[q]);
    float4 xv = ((const float4*)x)[idx];
    float4 rr;
    float n0 = (v.x - mu) * rstd * g.x + bt.x;  n0 *= sigmoidf_(n0);  rr.x = n0 + xv.x;
    float n1 = (v.y - mu) * rstd * g.y + bt.y;  n1 *= sigmoidf_(n1);  rr.y = n1 + xv.y;
    float n2 = (v.z - mu) * rstd * g.z + bt.z;  n2 *= sigmoidf_(n2);  rr.z = n2 + xv.z;
    float n3 = (v.w - mu) * rstd * g.w + bt.w;  n3 *= sigmoidf_(n3);  rr.w = n3 + xv.w;
    ((float4*)out)[idx] = rr;
}

// ---------------------------------------------------------------------------
extern "C" void kernel_launch(void* const* d_in, const int* in_sizes, int n_in,
                              void* d_out, int out_size) {
    const float* x         = (const float*)d_in[0];
    const int*   ei        = (const int*)  d_in[1];
    const float* edge_attr = (const float*)d_in[2];
    const float* Wl        = (const float*)d_in[3];
    const float* bl        = (const float*)d_in[4];
    const float* Wr        = (const float*)d_in[5];
    const float* br        = (const float*)d_in[6];
    const float* We        = (const float*)d_in[7];
    const float* att       = (const float*)d_in[8];
    const float* conv_bias = (const float*)d_in[9];
    const float* Wg1       = (const float*)d_in[10];
    const float* bg1       = (const float*)d_in[11];
    const float* Wg2       = (const float*)d_in[12];
    const float* bg2       = (const float*)d_in[13];
    const float* gamma     = (const float*)d_in[14];
    const float* beta      = (const float*)d_in[15];
    float* out = (float*)d_out;

    k_wcvt <<<6, 256>>>(We, Wg1);
    k_prep <<<(NN + 63) / 64, 256>>>(x, Wl, bl, Wr, br, out);
    k_edge <<<EE / ETPB, ETPB>>>(ei, edge_attr, att, Wg2, bg1, bg2, out);
    k_final<<<NN * 16 / TPB, TPB>>>(x, conv_bias, gamma, beta, out);
}

// round 13
// speedup vs baseline: 13.8945x; 1.0239x over previous
#include <cuda_runtime.h>
#include <cuda_fp16.h>

#define NN 100000
#define EE 1600000
#define TPB 256

typedef unsigned long long u64;
typedef unsigned int u32;

// ---- scratch (__device__ globals; no allocations allowed) ----
__device__ __half   g_xlh[NN * 64];   // fp16 x @ Wl + bl (logits + messages)
__device__ __half   g_xrh[NN * 64];   // fp16 x @ Wr + br (logits only)
__device__ float4   g_denom[NN];      // per-head softmax denominators
__device__ float2   g_gate2[NN];      // {gate_sum, degree} per target
__device__ __half   g_Wt[96 * 16];    // transposed fp16 [We | Wg1]: Wt[c][k]

__device__ __forceinline__ float sigmoidf_(float v) {
    return 1.f / (1.f + __expf(-v));
}
__device__ __forceinline__ u64 pack2(float lo, float hi) {
    u64 r; asm("mov.b64 %0, {%1,%2};" : "=l"(r) : "f"(lo), "f"(hi)); return r;
}
__device__ __forceinline__ void unpack2(u64 v, float& lo, float& hi) {
    asm("mov.b64 {%0,%1}, %2;" : "=f"(lo), "=f"(hi) : "l"(v));
}
__device__ __forceinline__ void fma2(u64& d, u64 a, u64 b) {
    asm("fma.rn.f32x2 %0, %1, %2, %0;" : "+l"(d) : "l"(a), "l"(b));
}
__device__ __forceinline__ void red4(float* p, float a, float b, float c, float d) {
    asm volatile("red.global.add.v4.f32 [%0], {%1,%2,%3,%4};"
                 :: "l"(p), "f"(a), "f"(b), "f"(c), "f"(d) : "memory");
}
__device__ __forceinline__ void red2(float* p, float a, float b) {
    asm volatile("red.global.add.v2.f32 [%0], {%1,%2};"
                 :: "l"(p), "f"(a), "f"(b) : "memory");
}
__device__ __forceinline__ float leaky(float m) { return fmaxf(m, 0.2f * m); }
__device__ __forceinline__ void cpa16(__half* smem_dst, const __half* gsrc) {
    unsigned d = (unsigned)__cvta_generic_to_shared(smem_dst);
    asm volatile("cp.async.ca.shared.global [%0], [%1], 16;"
                 :: "r"(d), "l"(gsrc) : "memory");
}
__device__ __forceinline__ unsigned h2_bits(__half2 v) {
    return *reinterpret_cast<unsigned*>(&v);
}
// m16n8k16 row.col f16f16 -> f32, D==C accumulate in place
__device__ __forceinline__ void mma16816(float& d0, float& d1, float& d2, float& d3,
                                         u32 a0, u32 a1, u32 a2, u32 a3,
                                         u32 b0, u32 b1) {
    asm volatile(
        "mma.sync.aligned.m16n8k16.row.col.f32.f16.f16.f32 "
        "{%0,%1,%2,%3}, {%4,%5,%6,%7}, {%8,%9}, {%0,%1,%2,%3};"
        : "+f"(d0), "+f"(d1), "+f"(d2), "+f"(d3)
        : "r"(a0), "r"(a1), "r"(a2), "r"(a3), "r"(b0), "r"(b1));
}

// ---------------------------------------------------------------------------
// Kernel 0: build transposed fp16 weight matrix Wt[96][16] = [We | Wg1]^T
// ---------------------------------------------------------------------------
__global__ void k_wcvt(const float* __restrict__ We, const float* __restrict__ Wg1) {
    int i = blockIdx.x * blockDim.x + threadIdx.x;    // 1536 elements
    if (i < 96 * 16) {
        int c = i >> 4, k = i & 15;
        float v = (c < 64) ? We[k * 64 + c] : Wg1[k * 32 + (c - 64)];
        g_Wt[i] = __float2half_rn(v);
    }
}

// ---------------------------------------------------------------------------
// Kernel 1: node transforms (fp16 out) + init accumulators + zero d_out.
// ---------------------------------------------------------------------------
__global__ void __launch_bounds__(256) k_prep(
        const float* __restrict__ x,
        const float* __restrict__ Wl, const float* __restrict__ bl,
        const float* __restrict__ Wr, const float* __restrict__ br,
        float* __restrict__ out) {
    __shared__ __align__(16) float Ws[64 * 128];
    __shared__ __align__(16) float xs[64 * 64];
    int t = threadIdx.x;
    int nb = blockIdx.x * 64;

#pragma unroll
    for (int i = 0; i < 16; i++) {
        int idx = t + i * 256;
        int k = idx >> 6, c = idx & 63;
        Ws[k * 128 + c]      = Wl[idx];
        Ws[k * 128 + 64 + c] = Wr[idx];
    }
#pragma unroll
    for (int i = 0; i < 16; i++) {
        int idx = t + i * 256;
        int n = nb + (idx >> 6);
        bool ok = n < NN;
        xs[idx] = ok ? x[(size_t)n * 64 + (idx & 63)] : 0.f;
        if (ok) out[(size_t)n * 64 + (idx & 63)] = 0.f;
    }
    if (t < 64) {
        int n = nb + t;
        if (n < NN) {
            g_denom[n] = make_float4(0.f, 0.f, 0.f, 0.f);
            g_gate2[n] = make_float2(0.f, 0.f);
        }
    }
    __syncthreads();

    int cg = t & 31, ng = t >> 5;
    int c0 = cg * 4;
    const float* bsrc = (c0 < 64) ? (bl + c0) : (br + (c0 - 64));
    float4 bias = *(const float4*)bsrc;

    u64 acc[8][2];
#pragma unroll
    for (int j = 0; j < 8; j++) {
        acc[j][0] = pack2(bias.x, bias.y);
        acc[j][1] = pack2(bias.z, bias.w);
    }

    for (int k4 = 0; k4 < 16; k4++) {
        float4 xv[8];
#pragma unroll
        for (int j = 0; j < 8; j++)
            xv[j] = *(const float4*)&xs[(ng * 8 + j) * 64 + k4 * 4];
#pragma unroll
        for (int kk = 0; kk < 4; kk++) {
            float4 wv = *(const float4*)&Ws[(k4 * 4 + kk) * 128 + c0];
            u64 w01 = pack2(wv.x, wv.y), w23 = pack2(wv.z, wv.w);
#pragma unroll
            for (int j = 0; j < 8; j++) {
                float xsc = (kk == 0) ? xv[j].x : (kk == 1) ? xv[j].y
                          : (kk == 2) ? xv[j].z : xv[j].w;
                u64 xx = pack2(xsc, xsc);
                fma2(acc[j][0], xx, w01);
                fma2(acc[j][1], xx, w23);
            }
        }
    }

    __half* dsth = (c0 < 64) ? g_xlh : g_xrh;
    int cc = c0 & 63;
#pragma unroll
    for (int j = 0; j < 8; j++) {
        int n = nb + ng * 8 + j;
        if (n < NN) {
            float o0, o1, o2, o3;
            unpack2(acc[j][0], o0, o1);
            unpack2(acc[j][1], o2, o3);
            uint2 p;
            p.x = h2_bits(__floats2half2_rn(o0, o1));
            p.y = h2_bits(__floats2half2_rn(o2, o3));
            *(uint2*)&dsth[(size_t)n * 64 + cc] = p;
        }
    }
}

// ---------------------------------------------------------------------------
// Kernel 2 (fused edge pass, tensor-core matmuls, R12 + two changes):
//   1. eag loaded COALESCED (lane = consecutive float4) and transposed into
//      the fp16 EA tile via smem — 16 L1 wavefronts instead of 64.
//   2. EA stride 24 -> 20 halfs: smem/block 46.5 -> 45.4KB -> 5 blocks/SM.
// ---------------------------------------------------------------------------
#define ETPB 128
#define RST 72                              // halfs per staged xl/xr row
#define EAST 20                             // halfs per ea row (16 + 4 pad)

__global__ void __launch_bounds__(ETPB) k_edge(
        const int* __restrict__ ei, const float* __restrict__ eag,
        const float* __restrict__ att, const float* __restrict__ Wg2,
        const float* __restrict__ bg1, const float* __restrict__ bg2p,
        float* __restrict__ out) {
    __shared__ __align__(16) __half sXL[4][32 * RST];
    __shared__ __align__(16) __half sXR[4][32 * RST];   // meta reuses this later
    __shared__ __align__(16) __half sEA[4][32 * EAST];
    __shared__ __align__(16) __half sWt[96 * 16];
    __shared__ __align__(16) float  sAtt[64];
    __shared__ __align__(8)  float  sWg2[32];
    __shared__ __align__(8)  float  sBg1[32];

    int t = threadIdx.x, lane = t & 31, w = t >> 5;
    __half* XL = sXL[w];
    __half* XR = sXR[w];
    __half* EA = sEA[w];

    // block-wide: stage weights (cp.async) + small params (LDG->STS)
    for (int i = t; i < 192; i += ETPB)
        cpa16(&sWt[i * 8], &g_Wt[i * 8]);
    if (t < 64) sAtt[t] = att[t];
    if (t >= 64 && t < 96)  sWg2[t - 64] = Wg2[t - 64];
    if (t >= 96 && t < 128) sBg1[t - 96] = bg1[t - 96];

    int e = blockIdx.x * ETPB + t;          // EE % ETPB == 0
    int src = ei[e];
    int tgt = ei[EE + e];

    // per-warp: stage full fp16 xl/xr rows (cp.async, 4 rows/line per instr)
    int rlane = lane >> 3;
    int off8  = (lane & 7) * 8;
#pragma unroll
    for (int i = 0; i < 8; i++) {
        int r  = i * 4 + rlane;
        int s  = __shfl_sync(0xFFFFFFFFu, src, r);
        int tg = __shfl_sync(0xFFFFFFFFu, tgt, r);
        cpa16(&XL[r * RST + off8], g_xlh + (size_t)s  * 64 + off8);
        cpa16(&XR[r * RST + off8], g_xrh + (size_t)tg * 64 + off8);
    }
    asm volatile("cp.async.commit_group;" ::: "memory");

    // coalesced eag load (4 lines/instr) + fp16 transpose into EA[32][20]
    {
        const float4* eabase = (const float4*)eag
                             + (size_t)(blockIdx.x * ETPB + 32 * w) * 4;
#pragma unroll
        for (int i = 0; i < 4; i++) {
            int j = lane + 32 * i;           // float4 index in warp's 2KB block
            float4 v = eabase[j];
            int ed = j >> 2, qq = j & 3;
            uint2 p;
            p.x = h2_bits(__floats2half2_rn(v.x, v.y));
            p.y = h2_bits(__floats2half2_rn(v.z, v.w));
            *(uint2*)&EA[ed * EAST + qq * 4] = p;
        }
    }
    float bg2v = bg2p[0];

    asm volatile("cp.async.wait_group 0;" ::: "memory");
    __syncthreads();                         // sWt ready + EA/XL/XR RAW

    int gr = lane >> 2;                      // group row (0..7)
    int q  = lane & 3;                       // thread in group (0..3)

    // ---- A fragments: two m-tiles (edges 0-15, 16-31) ----
    u32 a0m0 = *(const u32*)&EA[gr * EAST + 2 * q];
    u32 a1m0 = *(const u32*)&EA[(gr + 8) * EAST + 2 * q];
    u32 a2m0 = *(const u32*)&EA[gr * EAST + 2 * q + 8];
    u32 a3m0 = *(const u32*)&EA[(gr + 8) * EAST + 2 * q + 8];
    u32 a0m1 = *(const u32*)&EA[(gr + 16) * EAST + 2 * q];
    u32 a1m1 = *(const u32*)&EA[(gr + 24) * EAST + 2 * q];
    u32 a2m1 = *(const u32*)&EA[(gr + 16) * EAST + 2 * q + 8];
    u32 a3m1 = *(const u32*)&EA[(gr + 24) * EAST + 2 * q + 8];

    float ap[4][4] = {};                     // alpha partials [row-slot][head]
    float gp[4]    = {0.f, 0.f, 0.f, 0.f};   // gate partials per row-slot

#pragma unroll
    for (int nt = 0; nt < 12; nt++) {
        u32 b0 = *(const u32*)&sWt[(8 * nt + gr) * 16 + 2 * q];
        u32 b1 = *(const u32*)&sWt[(8 * nt + gr) * 16 + 2 * q + 8];

#pragma unroll
        for (int mt = 0; mt < 2; mt++) {
            float d0 = 0.f, d1 = 0.f, d2 = 0.f, d3 = 0.f;
            if (mt == 0) mma16816(d0, d1, d2, d3, a0m0, a1m0, a2m0, a3m0, b0, b1);
            else         mma16816(d0, d1, d2, d3, a0m1, a1m1, a2m1, a3m1, b0, b1);

            int r0 = gr + 16 * mt;           // rows r0 (d0,d1) and r0+8 (d2,d3)
            if (nt < 8) {                    // ---- attention head nt>>1 ----
                int col = 8 * nt + 2 * q;
                int h   = nt >> 1;
                float2 attv = *(const float2*)&sAtt[col];
                __half2 xl2 = *(const __half2*)&XL[r0 * RST + col];
                __half2 xr2 = *(const __half2*)&XR[r0 * RST + col];
                float2 f = __half22float2(__hadd2(xl2, xr2));
                float m0 = d0 + f.x, m1 = d1 + f.y;
                ap[2 * mt][h] += leaky(m0) * attv.x + leaky(m1) * attv.y;
                xl2 = *(const __half2*)&XL[(r0 + 8) * RST + col];
                xr2 = *(const __half2*)&XR[(r0 + 8) * RST + col];
                f = __half22float2(__hadd2(xl2, xr2));
                m0 = d2 + f.x; m1 = d3 + f.y;
                ap[2 * mt + 1][h] += leaky(m0) * attv.x + leaky(m1) * attv.y;
            } else {                         // ---- gate hidden units ----
                int hc = 8 * (nt - 8) + 2 * q;
                float2 b1v = *(const float2*)&sBg1[hc];
                float2 w2v = *(const float2*)&sWg2[hc];
                float h0 = d0 + b1v.x, h1 = d1 + b1v.y;
                gp[2 * mt]     += h0 * sigmoidf_(h0) * w2v.x +
                                  h1 * sigmoidf_(h1) * w2v.y;
                h0 = d2 + b1v.x; h1 = d3 + b1v.y;
                gp[2 * mt + 1] += h0 * sigmoidf_(h0) * w2v.x +
                                  h1 * sigmoidf_(h1) * w2v.y;
            }
        }
    }

    // ---- quad reductions (lanes sharing gr) ----
#pragma unroll
    for (int s = 0; s < 4; s++) {
#pragma unroll
        for (int h = 0; h < 4; h++) {
            ap[s][h] += __shfl_xor_sync(0xFFFFFFFFu, ap[s][h], 1);
            ap[s][h] += __shfl_xor_sync(0xFFFFFFFFu, ap[s][h], 2);
        }
        gp[s] += __shfl_xor_sync(0xFFFFFFFFu, gp[s], 1);
        gp[s] += __shfl_xor_sync(0xFFFFFFFFu, gp[s], 2);
    }

    // lane q of each quad finalizes row r = gr + 8q
    int r = gr + 8 * q;
    float e0 = __expf(ap[q][0]);
    float e1 = __expf(ap[q][1]);
    float e2 = __expf(ap[q][2]);
    float e3 = __expf(ap[q][3]);
    float gate = sigmoidf_(gp[q] + bg2v);
    int tgt_r = __shfl_sync(0xFFFFFFFFu, tgt, r);

    __syncwarp();                            // XR reads done -> reuse as meta
    float* mw = (float*)XR;                  // meta [32][8] floats
    mw[r * 8 + 0] = e0; mw[r * 8 + 1] = e1;
    mw[r * 8 + 2] = e2; mw[r * 8 + 3] = e3;
    mw[r * 8 + 4] = __int_as_float(tgt_r);
    red4((float*)&g_denom[tgt_r], e0, e1, e2, e3);
    red2((float*)&g_gate2[tgt_r], gate, 1.f);
    __syncwarp();

    // ---- phase C: messages from staged fp16 xl, cooperative red4 scatter ----
    int q15  = lane & 15;
    int rsel = lane >> 4;
    int h_c  = q15 >> 2;
#pragma unroll
    for (int i = 0; i < 16; i++) {
        int rr   = 2 * i + rsel;
        float a  = mw[rr * 8 + h_c];
        int tg   = __float_as_int(mw[rr * 8 + 4]);
        uint2 hv = *(const uint2*)&XL[rr * RST + q15 * 4];
        float2 f01 = __half22float2(*(const __half2*)&hv.x);
        float2 f23 = __half22float2(*(const __half2*)&hv.y);
        red4(out + (size_t)tg * 64 + q15 * 4,
             f01.x * a, f01.y * a, f23.x * a, f23.y * a);
    }
}

// ---------------------------------------------------------------------------
// Kernel 3: node epilogue — 16 threads/node, float4 lanes, global params.
// ---------------------------------------------------------------------------
__global__ void k_final(const float* __restrict__ x,
                        const float* __restrict__ conv_bias,
                        const float* __restrict__ gamma,
                        const float* __restrict__ beta,
                        float* __restrict__ out) {
    int gid = blockIdx.x * blockDim.x + threadIdx.x;
    int n = gid >> 4;
    int q = threadIdx.x & 15;
    int h = q >> 2;

    float2 gd = g_gate2[n];
    float mg = gd.x / fmaxf(gd.y, 1.f);
    float4 den4 = g_denom[n];
    float den = (h == 0) ? den4.x : (h == 1) ? den4.y : (h == 2) ? den4.z : den4.w;
    float inv = den > 0.f ? 1.f / den : 0.f;

    size_t idx = (size_t)n * 16 + q;
    float4 o  = ((const float4*)out)[idx];
    float4 cb = __ldg(&((const float4*)conv_bias)[q]);
    float4 v;
    v.x = (o.x * inv + cb.x) * mg;
    v.y = (o.y * inv + cb.y) * mg;
    v.z = (o.z * inv + cb.z) * mg;
    v.w = (o.w * inv + cb.w) * mg;

    float s  = v.x + v.y + v.z + v.w;
    float sq = v.x * v.x + v.y * v.y + v.z * v.z + v.w * v.w;
#pragma unroll
    for (int ofs = 1; ofs < 16; ofs <<= 1) {
        s  += __shfl_xor_sync(0xFFFFFFFFu, s,  ofs);
        sq += __shfl_xor_sync(0xFFFFFFFFu, sq, ofs);
    }
    float mu   = s * (1.f / 64.f);
    float var  = sq * (1.f / 64.f) - mu * mu;
    float rstd = rsqrtf(var + 1e-5f);

    float4 g  = __ldg(&((const float4*)gamma)[q]);
    float4 bt = __ldg(&((const float4*)beta)[q]);
    float4 xv = ((const float4*)x)[idx];
    float4 rr;
    float n0 = (v.x - mu) * rstd * g.x + bt.x;  n0 *= sigmoidf_(n0);  rr.x = n0 + xv.x;
    float n1 = (v.y - mu) * rstd * g.y + bt.y;  n1 *= sigmoidf_(n1);  rr.y = n1 + xv.y;
    float n2 = (v.z - mu) * rstd * g.z + bt.z;  n2 *= sigmoidf_(n2);  rr.z = n2 + xv.z;
    float n3 = (v.w - mu) * rstd * g.w + bt.w;  n3 *= sigmoidf_(n3);  rr.w = n3 + xv.w;
    ((float4*)out)[idx] = rr;
}

// ---------------------------------------------------------------------------
extern "C" void kernel_launch(void* const* d_in, const int* in_sizes, int n_in,
                              void* d_out, int out_size) {
    const float* x         = (const float*)d_in[0];
    const int*   ei        = (const int*)  d_in[1];
    const float* edge_attr = (const float*)d_in[2];
    const float* Wl        = (const float*)d_in[3];
    const float* bl        = (const float*)d_in[4];
    const float* Wr        = (const float*)d_in[5];
    const float* br        = (const float*)d_in[6];
    const float* We        = (const float*)d_in[7];
    const float* att       = (const float*)d_in[8];
    const float* conv_bias = (const float*)d_in[9];
    const float* Wg1       = (const float*)d_in[10];
    const float* bg1       = (const float*)d_in[11];
    const float* Wg2       = (const float*)d_in[12];
    const float* bg2       = (const float*)d_in[13];
    const float* gamma     = (const float*)d_in[14];
    const float* beta      = (const float*)d_in[15];
    float* out = (float*)d_out;

    k_wcvt <<<6, 256>>>(We, Wg1);
    k_prep <<<(NN + 63) / 64, 256>>>(x, Wl, bl, Wr, br, out);
    k_edge <<<EE / ETPB, ETPB>>>(ei, edge_attr, att, Wg2, bg1, bg2, out);
    k_final<<<NN * 16 / TPB, TPB>>>(x, conv_bias, gamma, beta, out);
}